// round 2
// baseline (speedup 1.0000x reference)
#include <cuda_runtime.h>
#include <math.h>

#define NRHO 28
#define MZ   29
#define KK   (NRHO * MZ)      /* 812 */
#define PAD  MZ               /* halo pad for +-MZ neighbor access */
#define XLEN (KK + 2 * PAD)   /* 870 */
#define LM   550              /* Lanczos steps */
#define NT   256

// Block-wide f32 sum with broadcast. 3 barriers (last one protects red[] reuse).
__device__ __forceinline__ float blockReduceSum(float v, float* red) {
    const unsigned full = 0xffffffffu;
    #pragma unroll
    for (int o = 16; o; o >>= 1) v += __shfl_down_sync(full, v, o);
    int lane = threadIdx.x & 31;
    int wid  = threadIdx.x >> 5;
    if (lane == 0) red[wid] = v;
    __syncthreads();
    if (wid == 0) {
        float w = (lane < (NT / 32)) ? red[lane] : 0.f;
        #pragma unroll
        for (int o = (NT / 64); o; o >>= 1) w += __shfl_down_sync(full, w, o);
        if (lane == 0) red[0] = w;
    }
    __syncthreads();
    float r = red[0];
    __syncthreads();
    return r;
}

// Symmetrize an off-diagonal pair: sign-preserving geometric mean.
// (Diagonal similarity D A D^-1 -> symmetric S with S_ij = sgn(A_ij)*sqrt(A_ij*A_ji).)
__device__ __forceinline__ float symb(float up, float dn) {
    float r = sqrtf(fmaxf(up * dn, 0.f));
    return (up < 0.f) ? -r : r;
}

__global__ void __launch_bounds__(NT)
cyl_schrodinger_minEig_kernel(const int* __restrict__ nn,
                              const float* __restrict__ mf,
                              const float* __restrict__ lap,
                              float* __restrict__ out)
{
    __shared__ float dsh[KK];          // diag of S (lap diag + potential)
    __shared__ float szp[PAD + KK];    // S[i, i+1]  (z band), front-padded
    __shared__ float srp[PAD + KK];    // S[i, i+MZ] (rho band), front-padded
    __shared__ float xb[3][XLEN];      // x_prev / x_cur / x_next, halo-padded
    __shared__ float Ta[LM];           // tridiag alpha
    __shared__ float Tb[LM];           // tridiag beta (Tb[j] couples j-1,j)
    __shared__ float red[NT / 32];

    const int b   = blockIdx.x;
    const int tid = threadIdx.x;

    // ---- init: zero halos/buffers, extract + symmetrize bands, start vector ----
    for (int i = tid; i < XLEN; i += NT) { xb[0][i] = 0.f; xb[1][i] = 0.f; xb[2][i] = 0.f; }
    for (int i = tid; i < PAD;  i += NT) { szp[i] = 0.f; srp[i] = 0.f; }

    for (int i = tid; i < KK; i += NT) {
        dsh[i] = lap[(size_t)i * KK + i] + mf[(size_t)b * KK + i];
        float sz = 0.f;
        if (i + 1 < KK)
            sz = symb(lap[(size_t)i * KK + i + 1], lap[(size_t)(i + 1) * KK + i]);
        szp[PAD + i] = sz;
        float sr = 0.f;
        if (i + MZ < KK)
            sr = symb(lap[(size_t)i * KK + i + MZ], lap[(size_t)(i + MZ) * KK + i]);
        srp[PAD + i] = sr;
        // deterministic pseudo-random start vector (generic overlap w/ ground state)
        xb[0][PAD + i] = sinf(0.754f * (float)i + 0.5f) + 0.3f * sinf(2.113f * (float)i + 1.1f);
    }
    __syncthreads();

    // normalize x0
    {
        float nl = 0.f;
        for (int i = tid; i < KK; i += NT) { float v = xb[0][PAD + i]; nl += v * v; }
        float nrm = blockReduceSum(nl, red);
        float inv0 = rsqrtf(nrm);
        for (int i = tid; i < KK; i += NT) xb[0][PAD + i] *= inv0;
        __syncthreads();
    }

    // ---- Lanczos: 3-term recurrence on the 5-band symmetric operator ----
    int cur = 0, prv = 2, nxt = 1;     // xb[prv] is zero initially (beta0 = 0)
    float beta = 0.f;
    int meff = LM;

    for (int j = 0; j < LM; j++) {
        const float* xc = xb[cur];
        const float* xp = xb[prv];
        float*       xn = xb[nxt];

        float al = 0.f;
        float yv[4];
        #pragma unroll
        for (int t = 0; t < 4; t++) {
            int i = tid + t * NT;
            if (i < KK) {
                float xi = xc[PAD + i];
                float y  = dsh[i] * xi
                         + szp[PAD + i]      * xc[PAD + i + 1]
                         + szp[PAD + i - 1]  * xc[PAD + i - 1]
                         + srp[PAD + i]      * xc[PAD + i + MZ]
                         + srp[PAD + i - MZ] * xc[PAD + i - MZ];
                yv[t] = y;
                al += y * xi;
            } else {
                yv[t] = 0.f;
            }
        }
        float alpha = blockReduceSum(al, red);

        float bl = 0.f;
        float wv[4];
        #pragma unroll
        for (int t = 0; t < 4; t++) {
            int i = tid + t * NT;
            if (i < KK) {
                float w = yv[t] - alpha * xc[PAD + i] - beta * xp[PAD + i];
                wv[t] = w;
                bl += w * w;
            } else {
                wv[t] = 0.f;
            }
        }
        float b2 = blockReduceSum(bl, red);

        if (tid == 0) Ta[j] = alpha;
        if (b2 < 1e-12f) { meff = j + 1; break; }   // lucky breakdown (uniform)
        float bn = sqrtf(b2);
        if (tid == 0 && j + 1 < LM) Tb[j + 1] = bn;

        float invb = 1.f / bn;
        #pragma unroll
        for (int t = 0; t < 4; t++) {
            int i = tid + t * NT;
            if (i < KK) xn[PAD + i] = wv[t] * invb;
        }
        beta = bn;
        int tmp = prv; prv = cur; cur = nxt; nxt = tmp;
        __syncthreads();
    }
    __syncthreads();

    // ---- min eigenvalue of tridiagonal T via warp-parallel Sturm multisection ----
    if (tid < 32) {
        const unsigned full = 0xffffffffu;
        const int m = meff;

        // bounds: Gershgorin lower, min(diag) upper (Rayleigh quotients >= lambda_min)
        float lo = 1e30f, hi = 1e30f;
        for (int i = tid; i < m; i += 32) {
            float bi  = (i > 0)     ? fabsf(Tb[i])     : 0.f;
            float bip = (i + 1 < m) ? fabsf(Tb[i + 1]) : 0.f;
            lo = fminf(lo, Ta[i] - bi - bip);
            hi = fminf(hi, Ta[i]);
        }
        #pragma unroll
        for (int o = 16; o; o >>= 1) {
            lo = fminf(lo, __shfl_xor_sync(full, lo, o));
            hi = fminf(hi, __shfl_xor_sync(full, hi, o));
        }

        // 5 rounds of 33-way multisection: width / 33^5 ~ 1e-6 abs resolution
        for (int r = 0; r < 5; r++) {
            float step = (hi - lo) * (1.f / 33.f);
            float s = lo + step * (float)(tid + 1);
            int c = 0;
            float q = Ta[0] - s;
            if (q == 0.f) q = -1e-30f;
            c += (q < 0.f);
            for (int i = 1; i < m; i++) {
                float bb = Tb[i];
                q = (Ta[i] - s) - __fdividef(bb * bb, q);
                if (q == 0.f) q = -1e-30f;
                c += (q < 0.f);
            }
            unsigned mask = __ballot_sync(full, c > 0);
            if (mask) {
                int jj = __ffs(mask) - 1;   // first shift with an eigenvalue below it
                hi = lo + step * (float)(jj + 1);
                lo = lo + step * (float)jj;
            } else {
                lo = lo + step * 32.f;
            }
        }

        if (tid == 0) {
            float lam = 0.5f * (lo + hi);
            int occ = nn[b];
            occ = max(0, min(2, occ));
            out[b] = lam * (float)occ;
        }
    }
}

extern "C" void kernel_launch(void* const* d_in, const int* in_sizes, int n_in,
                              void* d_out, int out_size) {
    const int*   nn  = (const int*)d_in[0];    // num_nucleons [B,1] int32
    const float* mf  = (const float*)d_in[1];  // mean_fields [B,28,29] f32
    const float* lap = (const float*)d_in[2];  // laplacian [812,812] f32
    float* out = (float*)d_out;                // [B,1] f32
    int B = in_sizes[1] / KK;
    cyl_schrodinger_minEig_kernel<<<B, NT>>>(nn, mf, lap, out);
}

// round 4
// speedup vs baseline: 2.3104x; 2.3104x over previous
#include <cuda_runtime.h>
#include <math.h>

#define NRHO 28
#define MZ   29
#define KK   (NRHO * MZ)      /* 812 */
#define PAD  MZ               /* halo pad for +-MZ neighbor access */
#define XLEN (KK + 2 * PAD)   /* 870 */
#define LM   280              /* Lanczos steps */
#define NT   128
#define EPT  7                /* 128*7 = 896 >= 812 */

// Symmetrize an off-diagonal pair: sign-preserving geometric mean.
// (Diagonal similarity D A D^-1 -> symmetric S with S_ij = sgn(A_ij)*sqrt(A_ij*A_ji).)
__device__ __forceinline__ float symb(float up, float dn) {
    float r = sqrtf(fmaxf(up * dn, 0.f));
    return (up < 0.f) ? -r : r;
}

__global__ void __launch_bounds__(NT)
cyl_schrodinger_minEig_kernel(const int* __restrict__ nn,
                              const float* __restrict__ mf,
                              const float* __restrict__ lap,
                              float* __restrict__ out)
{
    __shared__ float dsh[KK];          // diag of S (lap diag + potential)
    __shared__ float szp[PAD + KK];    // S[i, i+1]  (z band), front-padded
    __shared__ float srp[PAD + KK];    // S[i, i+MZ] (rho band), front-padded
    __shared__ float xb[3][XLEN];      // x_prev / x_cur / x_next, halo-padded
    __shared__ float Ta[LM];           // tridiag alpha
    __shared__ float Tb[LM + 1];       // tridiag beta (Tb[j] couples j-1,j)
    __shared__ float redA[NT / 32];    // partial sums: y.x
    __shared__ float redS[NT / 32];    // partial sums: y.y

    const int b    = blockIdx.x;
    const int tid  = threadIdx.x;
    const int lane = tid & 31;
    const int wid  = tid >> 5;
    const unsigned full = 0xffffffffu;

    // ---- init: zero halos/buffers, extract + symmetrize bands, start vector ----
    for (int i = tid; i < XLEN; i += NT) { xb[0][i] = 0.f; xb[1][i] = 0.f; xb[2][i] = 0.f; }
    for (int i = tid; i < PAD;  i += NT) { szp[i] = 0.f; srp[i] = 0.f; }

    for (int i = tid; i < KK; i += NT) {
        dsh[i] = lap[(size_t)i * KK + i] + mf[(size_t)b * KK + i];
        float sz = 0.f;
        if (i + 1 < KK)
            sz = symb(lap[(size_t)i * KK + i + 1], lap[(size_t)(i + 1) * KK + i]);
        szp[PAD + i] = sz;
        float sr = 0.f;
        if (i + MZ < KK)
            sr = symb(lap[(size_t)i * KK + i + MZ], lap[(size_t)(i + MZ) * KK + i]);
        srp[PAD + i] = sr;
        // deterministic pseudo-random start vector (generic overlap w/ ground state)
        xb[0][PAD + i] = sinf(0.754f * (float)i + 0.5f) + 0.3f * sinf(2.113f * (float)i + 1.1f);
    }
    __syncthreads();

    // normalize x0 (single-barrier reduction)
    {
        float nl = 0.f;
        #pragma unroll
        for (int t = 0; t < EPT; t++) {
            int i = tid + t * NT;
            if (i < KK) { float v = xb[0][PAD + i]; nl += v * v; }
        }
        #pragma unroll
        for (int o = 16; o; o >>= 1) nl += __shfl_down_sync(full, nl, o);
        if (lane == 0) redA[wid] = nl;
        __syncthreads();
        float nrm = redA[0] + redA[1] + redA[2] + redA[3];
        float inv0 = rsqrtf(nrm);
        #pragma unroll
        for (int t = 0; t < EPT; t++) {
            int i = tid + t * NT;
            if (i < KK) xb[0][PAD + i] *= inv0;
        }
        __syncthreads();
    }

    // ---- Lanczos: 3-term recurrence, ONE reduction per iteration ----
    // beta_new^2 = ||y||^2 - alpha^2 - beta_old^2  (orthogonality of x, x_prev, w)
    int cur = 0, prv = 2, nxt = 1;     // xb[prv] is zero initially (beta0 = 0)
    float beta = 0.f;
    int meff = LM;

    for (int j = 0; j < LM; j++) {
        const float* xc = xb[cur];
        const float* xp = xb[prv];
        float*       xn = xb[nxt];

        float a_loc = 0.f, s_loc = 0.f;
        float yv[EPT], xv[EPT];
        #pragma unroll
        for (int t = 0; t < EPT; t++) {
            int i = tid + t * NT;
            if (i < KK) {
                float xi = xc[PAD + i];
                float y  = dsh[i] * xi
                         + szp[PAD + i]      * xc[PAD + i + 1]
                         + szp[PAD + i - 1]  * xc[PAD + i - 1]
                         + srp[PAD + i]      * xc[PAD + i + MZ]
                         + srp[PAD + i - MZ] * xc[PAD + i - MZ];
                yv[t] = y; xv[t] = xi;
                a_loc = fmaf(y, xi, a_loc);
                s_loc = fmaf(y, y, s_loc);
            } else { yv[t] = 0.f; xv[t] = 0.f; }
        }
        // dual warp reduction (two chains pipeline through the shuffle unit)
        #pragma unroll
        for (int o = 16; o; o >>= 1) {
            a_loc += __shfl_down_sync(full, a_loc, o);
            s_loc += __shfl_down_sync(full, s_loc, o);
        }
        if (lane == 0) { redA[wid] = a_loc; redS[wid] = s_loc; }
        __syncthreads();
        float alpha = (redA[0] + redA[1]) + (redA[2] + redA[3]);
        float sigma = (redS[0] + redS[1]) + (redS[2] + redS[3]);
        float b2 = sigma - alpha * alpha - beta * beta;

        if (tid == 0) Ta[j] = alpha;
        if (b2 < 1e-8f) { meff = j + 1; break; }    // uniform decision
        float bn = sqrtf(b2);
        if (tid == 0) Tb[j + 1] = bn;

        float invb = 1.f / bn;
        #pragma unroll
        for (int t = 0; t < EPT; t++) {
            int i = tid + t * NT;
            if (i < KK)
                xn[PAD + i] = (yv[t] - alpha * xv[t] - beta * xp[PAD + i]) * invb;
        }
        beta = bn;
        int tmp = prv; prv = cur; cur = nxt; nxt = tmp;
        __syncthreads();   // protects x_next for next stencil AND redA/redS reuse
    }
    __syncthreads();

    // ---- min eigenvalue of tridiagonal T via warp-parallel Sturm multisection ----
    if (tid < 32) {
        const int m = meff;

        // bounds: Gershgorin lower, min(diag) upper (Rayleigh quotients >= lambda_min)
        float lo = 1e30f, hi = 1e30f;
        for (int i = lane; i < m; i += 32) {
            float bi  = (i > 0)     ? fabsf(Tb[i])     : 0.f;
            float bip = (i + 1 < m) ? fabsf(Tb[i + 1]) : 0.f;
            lo = fminf(lo, Ta[i] - bi - bip);
            hi = fminf(hi, Ta[i]);
        }
        #pragma unroll
        for (int o = 16; o; o >>= 1) {
            lo = fminf(lo, __shfl_xor_sync(full, lo, o));
            hi = fminf(hi, __shfl_xor_sync(full, hi, o));
        }

        // 5 rounds of 33-way multisection: width / 33^5 ~ 1e-6 abs resolution
        for (int r = 0; r < 5; r++) {
            float step = (hi - lo) * (1.f / 33.f);
            float s = lo + step * (float)(lane + 1);
            int c = 0;
            float q = Ta[0] - s;
            if (q == 0.f) q = -1e-30f;
            c += (q < 0.f);
            for (int i = 1; i < m; i++) {
                float bb = Tb[i];
                q = (Ta[i] - s) - __fdividef(bb * bb, q);
                if (q == 0.f) q = -1e-30f;
                c += (q < 0.f);
            }
            unsigned mask = __ballot_sync(full, c > 0);
            if (mask) {
                int jj = __ffs(mask) - 1;   // first shift with an eigenvalue below it
                hi = lo + step * (float)(jj + 1);
                lo = lo + step * (float)jj;
            } else {
                lo = lo + step * 32.f;
            }
        }

        if (lane == 0) {
            float lam = 0.5f * (lo + hi);
            int occ = nn[b];
            occ = max(0, min(2, occ));
            out[b] = lam * (float)occ;
        }
    }
}

extern "C" void kernel_launch(void* const* d_in, const int* in_sizes, int n_in,
                              void* d_out, int out_size) {
    const int*   nn  = (const int*)d_in[0];    // num_nucleons [B,1] int32
    const float* mf  = (const float*)d_in[1];  // mean_fields [B,28,29] f32
    const float* lap = (const float*)d_in[2];  // laplacian [812,812] f32
    float* out = (float*)d_out;                // [B,1] f32
    int B = in_sizes[1] / KK;
    cyl_schrodinger_minEig_kernel<<<B, NT>>>(nn, mf, lap, out);
}

// round 5
// speedup vs baseline: 6.4619x; 2.7969x over previous
#include <cuda_runtime.h>
#include <math.h>

#define NRHO 28
#define MZ   29
#define KK   (NRHO * MZ)      /* 812 */
#define PAD  MZ               /* halo pad for +-MZ neighbor access */
#define XLEN (KK + 2 * PAD)   /* 870 */
#define LM   176              /* Lanczos steps */
#define NT   128
#define EPT  7                /* 128*7 = 896 >= 812 */

// Symmetrize an off-diagonal pair: sign-preserving geometric mean.
// (Diagonal similarity D A D^-1 -> symmetric S with S_ij = sgn(A_ij)*sqrt(A_ij*A_ji).)
__device__ __forceinline__ float symb(float up, float dn) {
    float r = sqrtf(fmaxf(up * dn, 0.f));
    return (up < 0.f) ? -r : r;
}

__global__ void __launch_bounds__(NT)
cyl_schrodinger_minEig_kernel(const int* __restrict__ nn,
                              const float* __restrict__ mf,
                              const float* __restrict__ lap,
                              float* __restrict__ out)
{
    __shared__ float dsh[KK];          // diag of S (lap diag + potential)
    __shared__ float szp[PAD + KK];    // S[i, i+1]  (z band), front-padded
    __shared__ float srp[PAD + KK];    // S[i, i+MZ] (rho band), front-padded
    __shared__ float xs[2][XLEN];      // published x, ping-pong, halo-padded
    __shared__ float Ta[LM];           // tridiag alpha
    __shared__ float Tb[LM + 1];       // tridiag beta (Tb[j] couples j-1,j)
    __shared__ float redA[4];          // partial sums: y.x
    __shared__ float redS[4];          // partial sums: y.y

    const int b    = blockIdx.x;
    const int tid  = threadIdx.x;
    const int lane = tid & 31;
    const int wid  = tid >> 5;
    const unsigned full = 0xffffffffu;

    // ---- init: zero buffers/halos, extract + symmetrize bands, start vector ----
    for (int i = tid; i < XLEN; i += NT) { xs[0][i] = 0.f; xs[1][i] = 0.f; }
    for (int i = tid; i < PAD;  i += NT) { szp[i] = 0.f; srp[i] = 0.f; }

    float v0[EPT];
    #pragma unroll
    for (int t = 0; t < EPT; t++) {
        int i = tid + t * NT;
        if (i < KK) {
            dsh[i] = lap[(size_t)i * KK + i] + mf[(size_t)b * KK + i];
            float sz = 0.f;
            if (i + 1 < KK)
                sz = symb(lap[(size_t)i * KK + i + 1], lap[(size_t)(i + 1) * KK + i]);
            szp[PAD + i] = sz;
            float sr = 0.f;
            if (i + MZ < KK)
                sr = symb(lap[(size_t)i * KK + i + MZ], lap[(size_t)(i + MZ) * KK + i]);
            srp[PAD + i] = sr;
            // deterministic pseudo-random start vector
            v0[t] = sinf(0.754f * (float)i + 0.5f) + 0.3f * sinf(2.113f * (float)i + 1.1f);
        } else {
            v0[t] = 0.f;
        }
    }
    __syncthreads();   // bands + halos visible

    // ---- normalize x0 (values still in registers) ----
    float nl = 0.f;
    #pragma unroll
    for (int t = 0; t < EPT; t++) nl = fmaf(v0[t], v0[t], nl);
    #pragma unroll
    for (int o = 16; o; o >>= 1) nl += __shfl_down_sync(full, nl, o);
    if (lane == 0) redA[wid] = nl;
    __syncthreads();
    float inv0 = rsqrtf((redA[0] + redA[1]) + (redA[2] + redA[3]));

    // ---- register-resident state: own x chunk, prev chunk, band coefficients ----
    float xcur[EPT], xprv[EPT];
    float c0[EPT], cz1[EPT], cz0[EPT], cr1[EPT], cr0[EPT];
    #pragma unroll
    for (int t = 0; t < EPT; t++) {
        int i = tid + t * NT;
        float xv = v0[t] * inv0;
        xcur[t] = xv; xprv[t] = 0.f;
        if (i < KK) {
            xs[0][PAD + i] = xv;
            c0[t]  = dsh[i];
            cz1[t] = szp[PAD + i];
            cz0[t] = szp[PAD + i - 1];
            cr1[t] = srp[PAD + i];
            cr0[t] = srp[PAD + i - MZ];
        } else {
            c0[t] = cz1[t] = cz0[t] = cr1[t] = cr0[t] = 0.f;
        }
    }
    __syncthreads();   // x0 published; redA safe for reuse

    // ---- Lanczos: 3-term recurrence, one fused reduction per iteration ----
    // beta_new^2 = ||y||^2 - alpha^2 - beta_old^2  (orthogonality of x, x_prev, w)
    float beta = 0.f;
    int meff = LM;

    for (int j = 0; j < LM; j++) {
        const float* __restrict__ xc = xs[j & 1];
        float*       __restrict__ xn = xs[(j & 1) ^ 1];

        float a_loc = 0.f, s_loc = 0.f;
        float yv[EPT];
        #pragma unroll
        for (int t = 0; t < EPT; t++) {
            int i  = tid + t * NT;
            int ii = (i < KK) ? i : 0;          // clamp loads; coeffs are 0 when inactive
            float y = c0[t] * xcur[t];
            y = fmaf(cz1[t], xc[PAD + ii + 1],  y);
            y = fmaf(cz0[t], xc[PAD + ii - 1],  y);
            y = fmaf(cr1[t], xc[PAD + ii + MZ], y);
            y = fmaf(cr0[t], xc[PAD + ii - MZ], y);
            yv[t] = y;
            a_loc = fmaf(y, xcur[t], a_loc);
            s_loc = fmaf(y, y, s_loc);
        }
        // dual warp reduction (two chains pipeline through the shuffle unit)
        #pragma unroll
        for (int o = 16; o; o >>= 1) {
            a_loc += __shfl_down_sync(full, a_loc, o);
            s_loc += __shfl_down_sync(full, s_loc, o);
        }
        if (lane == 0) { redA[wid] = a_loc; redS[wid] = s_loc; }
        __syncthreads();
        float alpha = (redA[0] + redA[1]) + (redA[2] + redA[3]);
        float sigma = (redS[0] + redS[1]) + (redS[2] + redS[3]);
        float b2 = sigma - alpha * alpha - beta * beta;

        if (tid == 0) Ta[j] = alpha;
        if (b2 < 1e-8f) { meff = j + 1; break; }    // uniform decision
        float invb = rsqrtf(b2);
        float bn   = b2 * invb;
        if (tid == 0) Tb[j + 1] = bn;

        #pragma unroll
        for (int t = 0; t < EPT; t++) {
            int i = tid + t * NT;
            float w  = yv[t] - alpha * xcur[t] - beta * xprv[t];
            float xv = w * invb;
            xprv[t] = xcur[t];
            xcur[t] = xv;
            if (i < KK) xn[PAD + i] = xv;
        }
        beta = bn;
        __syncthreads();   // publish x_next; protect redA/redS
    }
    __syncthreads();

    // ---- min eigenvalue of tridiagonal T via warp-parallel Sturm multisection ----
    if (tid < 32) {
        const int m = meff;

        // bounds: Gershgorin lower, min(diag) upper
        float lo = 1e30f, hi = 1e30f;
        for (int i = lane; i < m; i += 32) {
            float bi  = (i > 0)     ? fabsf(Tb[i])     : 0.f;
            float bip = (i + 1 < m) ? fabsf(Tb[i + 1]) : 0.f;
            lo = fminf(lo, Ta[i] - bi - bip);
            hi = fminf(hi, Ta[i]);
        }
        #pragma unroll
        for (int o = 16; o; o >>= 1) {
            lo = fminf(lo, __shfl_xor_sync(full, lo, o));
            hi = fminf(hi, __shfl_xor_sync(full, hi, o));
        }

        // 4 rounds of 33-way multisection: width / 33^4 ~ 1.3e-5 abs resolution
        for (int r = 0; r < 4; r++) {
            float step = (hi - lo) * (1.f / 33.f);
            float s = lo + step * (float)(lane + 1);
            int c = 0;
            float q = Ta[0] - s;
            if (q == 0.f) q = -1e-30f;
            c += (q < 0.f);
            for (int i = 1; i < m; i++) {
                float bb = Tb[i];
                q = (Ta[i] - s) - __fdividef(bb * bb, q);
                if (q == 0.f) q = -1e-30f;
                c += (q < 0.f);
            }
            unsigned mask = __ballot_sync(full, c > 0);
            if (mask) {
                int jj = __ffs(mask) - 1;   // first shift with an eigenvalue below it
                hi = lo + step * (float)(jj + 1);
                lo = lo + step * (float)jj;
            } else {
                lo = lo + step * 32.f;
            }
        }

        if (lane == 0) {
            float lam = 0.5f * (lo + hi);
            int occ = nn[b];
            occ = max(0, min(2, occ));
            out[b] = lam * (float)occ;
        }
    }
}

extern "C" void kernel_launch(void* const* d_in, const int* in_sizes, int n_in,
                              void* d_out, int out_size) {
    const int*   nn  = (const int*)d_in[0];    // num_nucleons [B,1] int32
    const float* mf  = (const float*)d_in[1];  // mean_fields [B,28,29] f32
    const float* lap = (const float*)d_in[2];  // laplacian [812,812] f32
    float* out = (float*)d_out;                // [B,1] f32
    int B = in_sizes[1] / KK;
    cyl_schrodinger_minEig_kernel<<<B, NT>>>(nn, mf, lap, out);
}

// round 6
// speedup vs baseline: 6.6375x; 1.0272x over previous
#include <cuda_runtime.h>
#include <math.h>

#define NRHO 28
#define MZ   29
#define KK   (NRHO * MZ)      /* 812 */
#define PAD  MZ               /* halo pad for +-MZ neighbor access */
#define XLEN (KK + 2 * PAD)   /* 870 */
#define LM   144              /* Lanczos steps */
#define NT   128
#define EPT  7                /* 128*7 = 896 >= 812 */

// Symmetrize an off-diagonal pair: sign-preserving geometric mean.
// (Diagonal similarity D A D^-1 -> symmetric S with S_ij = sgn(A_ij)*sqrt(A_ij*A_ji).)
__device__ __forceinline__ float symb(float up, float dn) {
    float r = sqrtf(fmaxf(up * dn, 0.f));
    return (up < 0.f) ? -r : r;
}

__global__ void __launch_bounds__(NT)
cyl_schrodinger_minEig_kernel(const int* __restrict__ nn,
                              const float* __restrict__ mf,
                              const float* __restrict__ lap,
                              float* __restrict__ out)
{
    __shared__ float dsh[KK];          // diag of S (lap diag + potential)
    __shared__ float szp[PAD + KK];    // S[i, i+1]  (z band), front-padded
    __shared__ float srp[PAD + KK];    // S[i, i+MZ] (rho band), front-padded
    __shared__ float ys[2][XLEN];      // published y vectors, ping-pong, halo-padded
    __shared__ float Ta[LM];           // tridiag alpha
    __shared__ float Tb[LM + 1];       // tridiag beta (Tb[j] couples j-1,j)
    __shared__ float redA[4];          // partial sums: y.x
    __shared__ float redS[4];          // partial sums: y.y
    __shared__ float bnd[2];           // Sturm bounds broadcast

    const int b    = blockIdx.x;
    const int tid  = threadIdx.x;
    const int lane = tid & 31;
    const int wid  = tid >> 5;
    const unsigned full = 0xffffffffu;

    // ---- init: zero buffers/halos, extract + symmetrize bands, start vector ----
    for (int i = tid; i < XLEN; i += NT) { ys[0][i] = 0.f; ys[1][i] = 0.f; }
    for (int i = tid; i < PAD;  i += NT) { szp[i] = 0.f; srp[i] = 0.f; }

    float v0[EPT];
    #pragma unroll
    for (int t = 0; t < EPT; t++) {
        int i = tid + t * NT;
        if (i < KK) {
            dsh[i] = lap[(size_t)i * KK + i] + mf[(size_t)b * KK + i];
            float sz = 0.f;
            if (i + 1 < KK)
                sz = symb(lap[(size_t)i * KK + i + 1], lap[(size_t)(i + 1) * KK + i]);
            szp[PAD + i] = sz;
            float sr = 0.f;
            if (i + MZ < KK)
                sr = symb(lap[(size_t)i * KK + i + MZ], lap[(size_t)(i + MZ) * KK + i]);
            srp[PAD + i] = sr;
            // deterministic pseudo-random start vector
            v0[t] = sinf(0.754f * (float)i + 0.5f) + 0.3f * sinf(2.113f * (float)i + 1.1f);
        } else {
            v0[t] = 0.f;
        }
    }
    __syncthreads();   // bands + halos visible

    // ---- normalize x0 (values still in registers) ----
    float nl = 0.f;
    #pragma unroll
    for (int t = 0; t < EPT; t++) nl = fmaf(v0[t], v0[t], nl);
    #pragma unroll
    for (int o = 16; o; o >>= 1) nl += __shfl_down_sync(full, nl, o);
    if (lane == 0) redA[wid] = nl;
    __syncthreads();
    float inv0 = rsqrtf((redA[0] + redA[1]) + (redA[2] + redA[3]));

    // ---- register-resident state ----
    // x1/x2: x_{j-1}, x_{j-2}; yr1/yr2: y_{j-1}, y_{j-2} (own chunks)
    float x1[EPT], x2[EPT], yr1[EPT], yr2[EPT];
    float c0[EPT], cz1[EPT], cz0[EPT], cr1[EPT], cr0[EPT];
    #pragma unroll
    for (int t = 0; t < EPT; t++) {
        int i = tid + t * NT;
        float xv = v0[t] * inv0;
        yr1[t] = xv;        // iter 0 treats published "y_{-1}" := x_0
        yr2[t] = 0.f;
        x1[t]  = 0.f; x2[t] = 0.f;
        if (i < KK) {
            ys[0][PAD + i] = xv;            // publish x0 into buffer 0
            c0[t]  = dsh[i];
            cz1[t] = szp[PAD + i];
            cz0[t] = szp[PAD + i - 1];
            cr1[t] = srp[PAD + i];
            cr0[t] = srp[PAD + i - MZ];
        } else {
            c0[t] = cz1[t] = cz0[t] = cr1[t] = cr0[t] = 0.f;
        }
    }
    __syncthreads();   // x0 published; redA safe for reuse

    // ---- Lanczos, ONE barrier per iteration ----
    // y_j = (S*yhat - a_prev*y1 - b_prev*y2) * invb   (yhat = published y_{j-1})
    // x_j = (y1 - a_prev*x1 - b_prev*x2) * invb
    // alpha_j = x_j.y_j ; sigma_j = y_j.y_j ; beta_{j+1}^2 = sigma - alpha^2 - beta_j^2
    float a_prev = 0.f, b_prev = 0.f, invb = 1.f, beta = 0.f;
    int meff = LM;

    for (int j = 0; j < LM; j++) {
        const float* __restrict__ yc = ys[j & 1];
        float*       __restrict__ yn = ys[(j & 1) ^ 1];

        float a_loc = 0.f, s_loc = 0.f;
        float ynew[EPT], xnew[EPT];
        #pragma unroll
        for (int t = 0; t < EPT; t++) {
            int i  = tid + t * NT;
            int ii = (i < KK) ? i : 0;          // clamp loads; coeffs are 0 when inactive
            float s = c0[t] * yr1[t];
            s = fmaf(cz1[t], yc[PAD + ii + 1],  s);
            s = fmaf(cz0[t], yc[PAD + ii - 1],  s);
            s = fmaf(cr1[t], yc[PAD + ii + MZ], s);
            s = fmaf(cr0[t], yc[PAD + ii - MZ], s);
            float yv = (s - a_prev * yr1[t] - b_prev * yr2[t]) * invb;
            float xv = (yr1[t] - a_prev * x1[t] - b_prev * x2[t]) * invb;
            ynew[t] = yv; xnew[t] = xv;
            if (i < KK) yn[PAD + i] = yv;       // publish early: covered by the one barrier
            a_loc = fmaf(yv, xv, a_loc);
            s_loc = fmaf(yv, yv, s_loc);
        }
        // dual warp reduction (two chains pipeline through the shuffle unit)
        #pragma unroll
        for (int o = 16; o; o >>= 1) {
            a_loc += __shfl_down_sync(full, a_loc, o);
            s_loc += __shfl_down_sync(full, s_loc, o);
        }
        if (lane == 0) { redA[wid] = a_loc; redS[wid] = s_loc; }
        __syncthreads();    // partials visible AND y_j fully published
        float alpha = (redA[0] + redA[1]) + (redA[2] + redA[3]);
        float sigma = (redS[0] + redS[1]) + (redS[2] + redS[3]);
        float b2 = sigma - alpha * alpha - beta * beta;

        if (tid == 0) Ta[j] = alpha;
        if (b2 < 1e-8f) { meff = j + 1; break; }    // uniform decision
        float ib = rsqrtf(b2);
        float bn = b2 * ib;
        if (tid == 0) Tb[j + 1] = bn;

        // rotate register state
        #pragma unroll
        for (int t = 0; t < EPT; t++) {
            x2[t]  = x1[t];  x1[t]  = xnew[t];
            yr2[t] = yr1[t]; yr1[t] = ynew[t];
        }
        a_prev = alpha; b_prev = beta; beta = bn; invb = ib;
        // NOTE: redA/redS rewritten only after next iteration's barrier — safe.
    }
    __syncthreads();   // Ta/Tb visible to all

    // ---- min eigenvalue of T: block-wide 129-way Sturm multisection ----
    {
        const int m = meff;

        // bounds: Gershgorin lower, min(diag) upper
        float lo = 1e30f, hi = 1e30f;
        for (int i = tid; i < m; i += NT) {
            float bi  = (i > 0)     ? fabsf(Tb[i])     : 0.f;
            float bip = (i + 1 < m) ? fabsf(Tb[i + 1]) : 0.f;
            lo = fminf(lo, Ta[i] - bi - bip);
            hi = fminf(hi, Ta[i]);
        }
        #pragma unroll
        for (int o = 16; o; o >>= 1) {
            lo = fminf(lo, __shfl_xor_sync(full, lo, o));
            hi = fminf(hi, __shfl_xor_sync(full, hi, o));
        }
        if (lane == 0) { redA[wid] = lo; redS[wid] = hi; }
        __syncthreads();
        lo = fminf(fminf(redA[0], redA[1]), fminf(redA[2], redA[3]));
        hi = fminf(fminf(redS[0], redS[1]), fminf(redS[2], redS[3]));

        // 3 rounds of 129-way multisection: width / 129^3 ~ 1.4e-5 abs resolution
        for (int r = 0; r < 3; r++) {
            float step = (hi - lo) * (1.f / 129.f);
            float s = lo + step * (float)(tid + 1);
            int c = 0;
            float q = Ta[0] - s;
            if (q == 0.f) q = -1e-30f;
            c += (q < 0.f);
            for (int i = 1; i < m; i++) {
                float bb = Tb[i];
                q = (Ta[i] - s) - __fdividef(bb * bb, q);
                if (q == 0.f) q = -1e-30f;
                c += (q < 0.f);
            }
            // shifts increase with tid; count(c==0) == index of first bracket with c>0
            int jj = __syncthreads_count(c == 0);
            hi = lo + step * (float)(jj + 1);   // jj==NT -> hi unchanged (== old hi)
            lo = lo + step * (float)jj;
        }

        if (tid == 0) {
            float lam = 0.5f * (lo + hi);
            int occ = nn[b];
            occ = max(0, min(2, occ));
            out[b] = lam * (float)occ;
        }
    }
}

extern "C" void kernel_launch(void* const* d_in, const int* in_sizes, int n_in,
                              void* d_out, int out_size) {
    const int*   nn  = (const int*)d_in[0];    // num_nucleons [B,1] int32
    const float* mf  = (const float*)d_in[1];  // mean_fields [B,28,29] f32
    const float* lap = (const float*)d_in[2];  // laplacian [812,812] f32
    float* out = (float*)d_out;                // [B,1] f32
    int B = in_sizes[1] / KK;
    cyl_schrodinger_minEig_kernel<<<B, NT>>>(nn, mf, lap, out);
}

// round 7
// speedup vs baseline: 10.4523x; 1.5747x over previous
#include <cuda_runtime.h>
#include <math.h>

#define NRHO 28
#define MZ   29
#define KK   (NRHO * MZ)      /* 812 */
#define PAD  MZ               /* halo pad for +-MZ neighbor access */
#define XLEN (KK + 2 * PAD)   /* 870 */
#define LM   112              /* Lanczos steps (even) */
#define NT   128
#define EPT  7                /* 128*7 = 896 >= 812 */

// Symmetrize an off-diagonal pair: sign-preserving geometric mean.
__device__ __forceinline__ float symb(float up, float dn) {
    float r = sqrtf(fmaxf(up * dn, 0.f));
    return (up < 0.f) ? -r : r;
}

__global__ void __launch_bounds__(NT)
cyl_schrodinger_minEig_kernel(const int* __restrict__ nn,
                              const float* __restrict__ mf,
                              const float* __restrict__ lap,
                              float* __restrict__ out)
{
    __shared__ float dsh[KK];          // diag of S (lap diag + potential)
    __shared__ float szp[PAD + KK];    // S[i, i+1]  (z band), front-padded
    __shared__ float srp[PAD + KK];    // S[i, i+MZ] (rho band), front-padded
    __shared__ float ys[2][XLEN];      // published y vectors, ping-pong, halo-padded
    __shared__ float Ta[LM];           // tridiag alpha
    __shared__ float Tb[LM + 1];       // tridiag beta (Tb[j] couples j-1,j)
    __shared__ float redA[2][4];       // partial sums e = y_j.y_{j-1}, parity-buffered
    __shared__ float redS[2][4];       // partial sums s = y_j.y_j

    const int b    = blockIdx.x;
    const int tid  = threadIdx.x;
    const int lane = tid & 31;
    const int wid  = tid >> 5;
    const unsigned full = 0xffffffffu;

    // ---- init: zero buffers/halos, extract + symmetrize bands, start vector ----
    for (int i = tid; i < XLEN; i += NT) { ys[0][i] = 0.f; ys[1][i] = 0.f; }
    for (int i = tid; i < PAD;  i += NT) { szp[i] = 0.f; srp[i] = 0.f; }

    float v0[EPT];
    #pragma unroll
    for (int t = 0; t < EPT; t++) {
        int i = tid + t * NT;
        if (i < KK) {
            dsh[i] = lap[(size_t)i * KK + i] + mf[(size_t)b * KK + i];
            float sz = 0.f;
            if (i + 1 < KK)
                sz = symb(lap[(size_t)i * KK + i + 1], lap[(size_t)(i + 1) * KK + i]);
            szp[PAD + i] = sz;
            float sr = 0.f;
            if (i + MZ < KK)
                sr = symb(lap[(size_t)i * KK + i + MZ], lap[(size_t)(i + MZ) * KK + i]);
            srp[PAD + i] = sr;
            // deterministic start vector (accuracy irrelevant, just generic)
            v0[t] = __sinf(0.754f * (float)i + 0.5f) + 0.3f * __sinf(2.113f * (float)i + 1.1f);
        } else {
            v0[t] = 0.f;
        }
    }
    __syncthreads();   // bands + halos visible

    // ---- normalize x0 (values still in registers) ----
    float nl = 0.f;
    #pragma unroll
    for (int t = 0; t < EPT; t++) nl = fmaf(v0[t], v0[t], nl);
    #pragma unroll
    for (int o = 16; o; o >>= 1) nl += __shfl_down_sync(full, nl, o);
    if (lane == 0) redA[0][wid] = nl;
    __syncthreads();
    float inv0 = rsqrtf((redA[0][0] + redA[0][1]) + (redA[0][2] + redA[0][3]));

    // ---- register-resident state: two y chunks (roles alternate), coefficients ----
    float ya[EPT], yb[EPT];            // ya = y_{-1} := x0, yb = y_{-2} := 0
    float c0[EPT], cz1[EPT], cz0[EPT], cr1[EPT], cr0[EPT];
    #pragma unroll
    for (int t = 0; t < EPT; t++) {
        int i = tid + t * NT;
        float xv = v0[t] * inv0;
        ya[t] = xv; yb[t] = 0.f;
        if (i < KK) {
            ys[0][PAD + i] = xv;            // publish x0 into buffer 0
            c0[t]  = dsh[i];
            cz1[t] = szp[PAD + i];
            cz0[t] = szp[PAD + i - 1];
            cr1[t] = srp[PAD + i];
            cr0[t] = srp[PAD + i - MZ];
        } else {
            c0[t] = cz1[t] = cz0[t] = cr1[t] = cr0[t] = 0.f;
        }
    }
    __syncthreads();   // x0 published; redA safe for reuse

    // ---- Lanczos, one barrier per step, y-only recurrence ----
    // y_j = (S*y_{j-1} - a_prev*y_{j-1} - b_prev*y_{j-2}) / beta_j
    // e_j = y_j.y_{j-1}; sigma_j = y_j.y_j
    // alpha_j = e_j/beta_j - alpha_{j-1};  beta_{j+1}^2 = sigma - alpha_j^2 - beta_j^2
    float a_prev = 0.f, b_prev = 0.f, bcur = 0.f, invb = 1.f;
    int meff = LM;

    auto step = [&](const float* __restrict__ yc, float* __restrict__ yn,
                    float (&Y1)[EPT], float (&Y2)[EPT], int j, int par) -> bool {
        float e_loc = 0.f, s_loc = 0.f;
        #pragma unroll
        for (int t = 0; t < EPT; t++) {
            int i  = tid + t * NT;
            int ii = (i < KK) ? i : 0;          // clamp loads; coeffs 0 when inactive
            float u = c0[t] * Y1[t];
            u = fmaf(cz1[t], yc[PAD + ii + 1],  u);
            u = fmaf(cz0[t], yc[PAD + ii - 1],  u);
            u = fmaf(cr1[t], yc[PAD + ii + MZ], u);
            u = fmaf(cr0[t], yc[PAD + ii - MZ], u);
            float yv = (u - a_prev * Y1[t] - b_prev * Y2[t]) * invb;
            e_loc = fmaf(yv, Y1[t], e_loc);
            s_loc = fmaf(yv, yv, s_loc);
            Y2[t] = yv;                         // overwrite dead y_{j-2} -> becomes y_j
            if (i < KK) yn[PAD + i] = yv;       // publish early, covered by the barrier
        }
        #pragma unroll
        for (int o = 16; o; o >>= 1) {
            e_loc += __shfl_down_sync(full, e_loc, o);
            s_loc += __shfl_down_sync(full, s_loc, o);
        }
        if (lane == 0) { redA[par][wid] = e_loc; redS[par][wid] = s_loc; }
        __syncthreads();                        // partials visible AND y_j published
        float e     = (redA[par][0] + redA[par][1]) + (redA[par][2] + redA[par][3]);
        float sigma = (redS[par][0] + redS[par][1]) + (redS[par][2] + redS[par][3]);
        float alpha = e * invb - a_prev;
        float b2 = sigma - alpha * alpha - bcur * bcur;

        if (tid == 0) Ta[j] = alpha;
        if (b2 < 1e-8f) { meff = j + 1; return true; }   // uniform decision
        float ib = rsqrtf(b2);
        float bn = b2 * ib;
        if (tid == 0) Tb[j + 1] = bn;
        a_prev = alpha; b_prev = bcur; bcur = bn; invb = ib;
        return false;
    };

    for (int j = 0; j < LM; j += 2) {
        if (step(ys[0], ys[1], ya, yb, j,     0)) break;   // yb <- y_j
        if (step(ys[1], ys[0], yb, ya, j + 1, 1)) break;   // ya <- y_{j+1}
    }
    __syncthreads();   // Ta/Tb visible to all

    // ---- min eigenvalue of T: block-wide 129-way Sturm multisection ----
    {
        const int m = meff;

        // bounds: Gershgorin lower, min(diag) upper
        float lo = 1e30f, hi = 1e30f;
        for (int i = tid; i < m; i += NT) {
            float bi  = (i > 0)     ? fabsf(Tb[i])     : 0.f;
            float bip = (i + 1 < m) ? fabsf(Tb[i + 1]) : 0.f;
            lo = fminf(lo, Ta[i] - bi - bip);
            hi = fminf(hi, Ta[i]);
        }
        #pragma unroll
        for (int o = 16; o; o >>= 1) {
            lo = fminf(lo, __shfl_xor_sync(full, lo, o));
            hi = fminf(hi, __shfl_xor_sync(full, hi, o));
        }
        if (lane == 0) { redA[0][wid] = lo; redS[0][wid] = hi; }
        __syncthreads();
        lo = fminf(fminf(redA[0][0], redA[0][1]), fminf(redA[0][2], redA[0][3]));
        hi = fminf(fminf(redS[0][0], redS[0][1]), fminf(redS[0][2], redS[0][3]));

        // 3 rounds of 129-way multisection via division-free Sturm continuants:
        //   p_i = (a_i - s) p_{i-1} - b_i^2 p_{i-2};  #eigs < s = #sign changes.
        // Branchless rescale every 4 steps against fp32 over/underflow.
        for (int r = 0; r < 3; r++) {
            float stepw = (hi - lo) * (1.f / 129.f);
            float s = lo + stepw * (float)(tid + 1);
            float pm1 = 1.f;
            float p   = Ta[0] - s;
            int c = (p < 0.f);
            for (int i = 1; i < m; i++) {
                float bb = Tb[i] * Tb[i];
                float pn = fmaf(Ta[i] - s, p, -bb * pm1);
                c += ((pn < 0.f) != (p < 0.f));
                pm1 = p; p = pn;
                if ((i & 3) == 3) {
                    float ap = fabsf(p);
                    float sc = ap > 1e15f ? 1e-25f : (ap < 1e-15f ? 1e25f : 1.f);
                    p *= sc; pm1 *= sc;
                }
            }
            // shifts increase with tid; count(c==0) == index of bracketing slice
            int jj = __syncthreads_count(c == 0);
            hi = lo + stepw * (float)(jj + 1);
            lo = lo + stepw * (float)jj;
        }

        if (tid == 0) {
            float lam = 0.5f * (lo + hi);
            int occ = nn[b];
            occ = max(0, min(2, occ));
            out[b] = lam * (float)occ;
        }
    }
}

extern "C" void kernel_launch(void* const* d_in, const int* in_sizes, int n_in,
                              void* d_out, int out_size) {
    const int*   nn  = (const int*)d_in[0];    // num_nucleons [B,1] int32
    const float* mf  = (const float*)d_in[1];  // mean_fields [B,28,29] f32
    const float* lap = (const float*)d_in[2];  // laplacian [812,812] f32
    float* out = (float*)d_out;                // [B,1] f32
    int B = in_sizes[1] / KK;
    cyl_schrodinger_minEig_kernel<<<B, NT>>>(nn, mf, lap, out);
}